// round 11
// baseline (speedup 1.0000x reference)
#include <cuda_runtime.h>
#include <cstdint>
#include <cstddef>

// Problem constants
#define SEQ   577
#define BB    64
#define DD    768
#define HH    12
#define KK    8
#define PP    576            // SEQ-1
#define ROWS  (PP*BB)        // 36864
#define S2    (SEQ*SEQ)      // 332929
#define EPSC  1e-8f
#define BETA_C  3.0f
#define GAMMA_C 5.0f

#define DBLK  1152           // 1152*32 = 36864 rows

// ---------------- scratch (static device globals; no allocation) -------------
__device__ __align__(16) float g_fg[ROWS];
__device__ __align__(16) float g_anom[ROWS];
__device__ __align__(16) float g_gate[ROWS];
__device__ __align__(16) float g_coeff[ROWS * KK];   // (1-g)-scaled after kc

// ---------------- helpers ----------------------------------------------------
typedef unsigned long long u64;

__device__ __forceinline__ float warp_sum(float v) {
    v += __shfl_xor_sync(0xffffffffu, v, 16);
    v += __shfl_xor_sync(0xffffffffu, v, 8);
    v += __shfl_xor_sync(0xffffffffu, v, 4);
    v += __shfl_xor_sync(0xffffffffu, v, 2);
    v += __shfl_xor_sync(0xffffffffu, v, 1);
    return v;
}
__device__ __forceinline__ float warp_max(float v) {
    v = fmaxf(v, __shfl_xor_sync(0xffffffffu, v, 16));
    v = fmaxf(v, __shfl_xor_sync(0xffffffffu, v, 8));
    v = fmaxf(v, __shfl_xor_sync(0xffffffffu, v, 4));
    v = fmaxf(v, __shfl_xor_sync(0xffffffffu, v, 2));
    v = fmaxf(v, __shfl_xor_sync(0xffffffffu, v, 1));
    return v;
}
__device__ __forceinline__ u64 pk2(float lo, float hi) {
    u64 r; asm("mov.b64 %0, {%1,%2};" : "=l"(r) : "f"(lo), "f"(hi)); return r;
}
__device__ __forceinline__ void up2(u64 v, float& lo, float& hi) {
    asm("mov.b64 {%0,%1}, %2;" : "=f"(lo), "=f"(hi) : "l"(v));
}
__device__ __forceinline__ u64 f2mul(u64 a, u64 b) {
    u64 d; asm("mul.rn.f32x2 %0, %1, %2;" : "=l"(d) : "l"(a), "l"(b)); return d;
}
__device__ __forceinline__ u64 f2fma(u64 a, u64 b, u64 c) {
    u64 d; asm("fma.rn.f32x2 %0, %1, %2, %3;" : "=l"(d) : "l"(a), "l"(b), "l"(c)); return d;
}

// 8-value warp reduction: 9 shuffles. Lane ends holding full sum of cp[(lane>>2)&7].
__device__ __forceinline__ float warp_sum8(const float* cp, int lane) {
    const bool b4 = (lane & 16) != 0;
    const bool b3 = (lane & 8) != 0;
    const bool b2 = (lane & 4) != 0;
    float v0, v1, v2, v3;
    {
        float s, r;
        s = b4 ? cp[0] : cp[4]; r = __shfl_xor_sync(0xffffffffu, s, 16);
        v0 = (b4 ? cp[4] : cp[0]) + r;
        s = b4 ? cp[1] : cp[5]; r = __shfl_xor_sync(0xffffffffu, s, 16);
        v1 = (b4 ? cp[5] : cp[1]) + r;
        s = b4 ? cp[2] : cp[6]; r = __shfl_xor_sync(0xffffffffu, s, 16);
        v2 = (b4 ? cp[6] : cp[2]) + r;
        s = b4 ? cp[3] : cp[7]; r = __shfl_xor_sync(0xffffffffu, s, 16);
        v3 = (b4 ? cp[7] : cp[3]) + r;
    }
    float w0, w1;
    {
        float s, r;
        s = b3 ? v0 : v2; r = __shfl_xor_sync(0xffffffffu, s, 8);
        w0 = (b3 ? v2 : v0) + r;
        s = b3 ? v1 : v3; r = __shfl_xor_sync(0xffffffffu, s, 8);
        w1 = (b3 ? v3 : v1) + r;
    }
    float u;
    {
        float s = b2 ? w0 : w1;
        float r = __shfl_xor_sync(0xffffffffu, s, 4);
        u = (b2 ? w1 : w0) + r;
    }
    u += __shfl_xor_sync(0xffffffffu, u, 2);
    u += __shfl_xor_sync(0xffffffffu, u, 1);
    return u;
}

// ---------------- Kernel AB -----------------------------------------------
// Blocks [0,64): A (fg mask), 192 threads, 3 patches/thread.
// Blocks [64,64+1152): B — 32 rows/block, 4 cols/thread, pc in regs.
//   Per row: coeff[8] + ss/st/tt → anomaly + raw coeff to global.
__global__ void __launch_bounds__(192) kab(const float* __restrict__ x,
                                           const float* __restrict__ text,
                                           const float* __restrict__ attn,
                                           const float* __restrict__ pc) {
    const int tid = threadIdx.x;
    const int lane = tid & 31, warp = tid >> 5;

    __shared__ float sp[8];
    __shared__ float bcast;
    __shared__ float redc[4 * 6 * 8];   // [row][warp][k]
    __shared__ float redq[4 * 6 * 3];   // [row][warp][ss,st,tt]

    if (blockIdx.x < 64) {
        // ---- A: foreground mask ----
        const int b = blockIdx.x;
        float a[3];
        #pragma unroll
        for (int j = 0; j < 3; j++) {
            const int p = tid + j * 192;
            const float* base = attn + (size_t)b * HH * (size_t)S2 + 1 + p;
            float s = 0.f;
            #pragma unroll
            for (int h = 0; h < HH; h++) s += __ldg(base + (size_t)h * S2);
            a[j] = s * (1.0f / 12.0f);
        }

        float v = warp_sum(a[0] + a[1] + a[2]);
        if (lane == 0) sp[warp] = v;
        __syncthreads();
        if (warp == 0) {
            float t = (lane < 6) ? sp[lane] : 0.f;
            t = warp_sum(t);
            if (lane == 0) bcast = t;
        }
        __syncthreads();
        const float mu = bcast * (1.0f / 576.0f);
        float d0 = a[0] - mu, d1 = a[1] - mu, d2 = a[2] - mu;
        __syncthreads();

        v = warp_sum(d0 * d0 + d1 * d1 + d2 * d2);
        if (lane == 0) sp[warp] = v;
        __syncthreads();
        if (warp == 0) {
            float t = (lane < 6) ? sp[lane] : 0.f;
            t = warp_sum(t);
            if (lane == 0) bcast = t;
        }
        __syncthreads();
        const float thrv = mu + 1.5f * sqrtf(bcast * (1.0f / 575.0f));
        #pragma unroll
        for (int j = 0; j < 3; j++)
            g_fg[(tid + j * 192) * BB + b] = (a[j] > thrv) ? 1.0f : 0.0f;
    } else {
        // ---- B: coeff + anomaly ----
        u64 pc0[KK], pc1[KK];
        #pragma unroll
        for (int k = 0; k < KK; k++) {
            const float4 v = __ldg((const float4*)pc + k * 192 + tid);
            pc0[k] = pk2(v.x, v.y);
            pc1[k] = pk2(v.z, v.w);
        }

        const int base = (int)(blockIdx.x - 64) * 32;

        for (int i0 = 0; i0 < 32; i0 += 4) {
            u64 x0[4], x1[4];
            #pragma unroll
            for (int j = 0; j < 4; j++) {
                const float4 xv = __ldg((const float4*)x +
                                        (size_t)(base + i0 + j + BB) * (DD / 4) + tid);
                x0[j] = pk2(xv.x, xv.y);
                x1[j] = pk2(xv.z, xv.w);
            }

            #pragma unroll
            for (int j = 0; j < 4; j++) {
                const int r = base + i0 + j;
                const int b = r & (BB - 1);
                const float4 tv = __ldg((const float4*)text + (size_t)b * (DD / 4) + tid);
                const u64 t0 = pk2(tv.x, tv.y);
                const u64 t1 = pk2(tv.z, tv.w);

                float cp[KK];
                #pragma unroll
                for (int k = 0; k < KK; k++) {
                    const u64 acc = f2fma(x1[j], pc1[k], f2mul(x0[j], pc0[k]));
                    float lo, hi; up2(acc, lo, hi);
                    cp[k] = lo + hi;
                }
                float q[KK];
                {
                    u64 acc = f2fma(x1[j], x1[j], f2mul(x0[j], x0[j]));
                    float lo, hi; up2(acc, lo, hi); q[0] = lo + hi;        // ss
                    acc = f2fma(x1[j], t1, f2mul(x0[j], t0));
                    up2(acc, lo, hi); q[1] = lo + hi;                      // st
                    acc = f2fma(t1, t1, f2mul(t0, t0));
                    up2(acc, lo, hi); q[2] = lo + hi;                      // tt
                    q[3] = q[4] = q[5] = q[6] = q[7] = 0.f;
                }
                const float u1 = warp_sum8(cp, lane);
                const float u2 = warp_sum8(q, lane);
                const int k = lane >> 2;
                if ((lane & 3) == 0) {
                    redc[(j * 6 + warp) * 8 + k] = u1;
                    if (k < 3) redq[(j * 6 + warp) * 3 + k] = u2;
                }
            }
            __syncthreads();
            if (tid < 32) {
                const int row = tid >> 3, k = tid & 7;
                float s = 0.f;
                #pragma unroll
                for (int w = 0; w < 6; w++) s += redc[(row * 6 + w) * 8 + k];
                g_coeff[(size_t)(base + i0 + row) * 8 + k] = s;
            } else if (tid < 36) {
                const int row = tid - 32;
                float ss = 0.f, st = 0.f, tt = 0.f;
                #pragma unroll
                for (int w = 0; w < 6; w++) {
                    ss += redq[(row * 6 + w) * 3 + 0];
                    st += redq[(row * 6 + w) * 3 + 1];
                    tt += redq[(row * 6 + w) * 3 + 2];
                }
                const float pn = sqrtf(ss);
                const float tn = sqrtf(tt);
                const float sim = st / (fmaxf(pn, EPSC) * fmaxf(tn, EPSC));
                g_anom[base + i0 + row] = pn * (1.0f - fmaxf(sim, 0.0f));
            }
            __syncthreads();
        }
    }
}

// ---------------- Kernel C: global stats + gate + coeff scaling --------------
__global__ void __launch_bounds__(1024) kc_stats() {
    const int tid = threadIdx.x;
    const int lane = tid & 31, w = tid >> 5;
    __shared__ float p0[32], p1[32], p2[32];
    __shared__ float bc[4];

    const float4* a4 = (const float4*)g_anom;
    const float4* f4 = (const float4*)g_fg;

    float n = 0.f, s1 = 0.f, mx = -3.0e38f;
    for (int i = tid; i < ROWS / 4; i += 1024) {
        const float4 av = a4[i];
        const float4 fv = f4[i];
        float bg;
        bg = 1.f - fv.x; n += bg; s1 += bg * av.x; mx = fmaxf(mx, av.x);
        bg = 1.f - fv.y; n += bg; s1 += bg * av.y; mx = fmaxf(mx, av.y);
        bg = 1.f - fv.z; n += bg; s1 += bg * av.z; mx = fmaxf(mx, av.z);
        bg = 1.f - fv.w; n += bg; s1 += bg * av.w; mx = fmaxf(mx, av.w);
    }
    n = warp_sum(n); s1 = warp_sum(s1); mx = warp_max(mx);
    if (lane == 0) { p0[w] = n; p1[w] = s1; p2[w] = mx; }
    __syncthreads();
    if (w == 0) {
        float a = warp_sum(p0[lane]);
        float b = warp_sum(p1[lane]);
        float c = warp_max(p2[lane]);
        if (lane == 0) { bc[0] = a; bc[1] = b; bc[2] = c; }
    }
    __syncthreads();
    const float N  = bc[0];
    const float mu = bc[1] / fmaxf(N, 1.0f);
    const float MX = bc[2];

    float s2 = 0.f;
    for (int i = tid; i < ROWS / 4; i += 1024) {
        const float4 av = a4[i];
        const float4 fv = f4[i];
        float d;
        d = av.x - mu; s2 += (1.f - fv.x) * d * d;
        d = av.y - mu; s2 += (1.f - fv.y) * d * d;
        d = av.z - mu; s2 += (1.f - fv.z) * d * d;
        d = av.w - mu; s2 += (1.f - fv.w) * d * d;
    }
    s2 = warp_sum(s2);
    if (lane == 0) p0[w] = s2;
    __syncthreads();
    if (w == 0) {
        float a = warp_sum(p0[lane]);
        if (lane == 0) {
            const float var = a / fmaxf(N - 1.0f, 1.0f);
            bc[3] = (N > 0.f) ? (mu + BETA_C * sqrtf(var)) : MX;
        }
    }
    __syncthreads();
    const float thr = bc[3];

    // gate per row + scale coeff by (1-gate)
    float4* c4 = (float4*)g_coeff;
    for (int r = tid; r < ROWS; r += 1024) {
        const float a = g_anom[r];
        const float f = g_fg[r];
        const float gg = f + (1.f - f) * (1.0f / (1.0f + __expf(-GAMMA_C * (thr - a))));
        g_gate[r] = gg;
        const float s = 1.0f - gg;
        float4 c0 = c4[r * 2], c1 = c4[r * 2 + 1];
        c0.x *= s; c0.y *= s; c0.z *= s; c0.w *= s;
        c1.x *= s; c1.y *= s; c1.z *= s; c1.w *= s;
        c4[r * 2] = c0; c4[r * 2 + 1] = c1;
    }
}

// ---------------- Kernel D: pure streaming blend -------------------------------
// out = gate*x + sum_k coeff'_k * pc_k   (coeff' pre-scaled by 1-gate).
// No shuffles, no barriers. Reverse block order for L2 reuse of x.
__global__ void __launch_bounds__(192) kd_out(const float* __restrict__ x,
                                              const float* __restrict__ pc,
                                              float* __restrict__ out) {
    const int tid = threadIdx.x;

    u64 pc0[KK], pc1[KK];
    #pragma unroll
    for (int k = 0; k < KK; k++) {
        const float4 v = __ldg((const float4*)pc + k * 192 + tid);
        pc0[k] = pk2(v.x, v.y);
        pc1[k] = pk2(v.z, v.w);
    }

    const int base = (DBLK - 1 - (int)blockIdx.x) * 32;

    #pragma unroll 4
    for (int i = 0; i < 32; i++) {
        const int r = base + i;
        const float4 xv = __ldg((const float4*)x + (size_t)(r + BB) * (DD / 4) + tid);
        const float4 cA = __ldg((const float4*)g_coeff + r * 2);
        const float4 cB = __ldg((const float4*)g_coeff + r * 2 + 1);
        const float g  = __ldg(&g_gate[r]);

        u64 cc = pk2(cA.x, cA.x);
        u64 q0 = f2mul(cc, pc0[0]);
        u64 q1 = f2mul(cc, pc1[0]);
        cc = pk2(cA.y, cA.y); q0 = f2fma(cc, pc0[1], q0); q1 = f2fma(cc, pc1[1], q1);
        cc = pk2(cA.z, cA.z); q0 = f2fma(cc, pc0[2], q0); q1 = f2fma(cc, pc1[2], q1);
        cc = pk2(cA.w, cA.w); q0 = f2fma(cc, pc0[3], q0); q1 = f2fma(cc, pc1[3], q1);
        cc = pk2(cB.x, cB.x); q0 = f2fma(cc, pc0[4], q0); q1 = f2fma(cc, pc1[4], q1);
        cc = pk2(cB.y, cB.y); q0 = f2fma(cc, pc0[5], q0); q1 = f2fma(cc, pc1[5], q1);
        cc = pk2(cB.z, cB.z); q0 = f2fma(cc, pc0[6], q0); q1 = f2fma(cc, pc1[6], q1);
        cc = pk2(cB.w, cB.w); q0 = f2fma(cc, pc0[7], q0); q1 = f2fma(cc, pc1[7], q1);

        const u64 x0 = pk2(xv.x, xv.y);
        const u64 x1 = pk2(xv.z, xv.w);
        const u64 g2 = pk2(g, g);
        const u64 o0 = f2fma(g2, x0, q0);
        const u64 o1 = f2fma(g2, x1, q1);
        float a0, a1, a2, a3;
        up2(o0, a0, a1);
        up2(o1, a2, a3);
        ((float4*)out)[(size_t)(r + BB) * (DD / 4) + tid] = make_float4(a0, a1, a2, a3);
    }
}

// ---------------- launch ------------------------------------------------------
extern "C" void kernel_launch(void* const* d_in, const int* in_sizes, int n_in,
                              void* d_out, int out_size) {
    const float* x    = (const float*)d_in[0];
    const float* attn = (const float*)d_in[1];
    const float* text = (const float*)d_in[2];
    const float* pc   = (const float*)d_in[3];
    float* out = (float*)d_out;

    // cls token pass-through: out[0] = x[0]
    cudaMemcpyAsync(out, x, (size_t)BB * DD * sizeof(float),
                    cudaMemcpyDeviceToDevice);

    kab<<<64 + DBLK, 192>>>(x, text, attn, pc);
    kc_stats<<<1, 1024>>>();
    kd_out<<<DBLK, 192>>>(x, pc, out);
}

// round 12
// speedup vs baseline: 1.7978x; 1.7978x over previous
#include <cuda_runtime.h>
#include <cstdint>
#include <cstddef>

// Problem constants
#define SEQ   577
#define BB    64
#define DD    768
#define HH    12
#define KK    8
#define PP    576            // SEQ-1
#define ROWS  (PP*BB)        // 36864
#define S2    (SEQ*SEQ)      // 332929
#define EPSC  1e-8f
#define BETA_C  3.0f
#define GAMMA_C 5.0f

#define DBLK  1152           // kernel D blocks: 1152*32 = 36864 rows

// ---------------- scratch (static device globals; no allocation) -------------
__device__ __align__(16) float g_fg[ROWS];
__device__ __align__(16) float g_anom[ROWS];
__device__ __align__(16) float g_gate[ROWS];
// global stat accumulators (zeroed by kab block 0 each launch)
__device__ double   g_n, g_s1, g_s2;
__device__ unsigned g_mxbits;

// ---------------- helpers ----------------------------------------------------
typedef unsigned long long u64;

__device__ __forceinline__ float warp_sum(float v) {
    v += __shfl_xor_sync(0xffffffffu, v, 16);
    v += __shfl_xor_sync(0xffffffffu, v, 8);
    v += __shfl_xor_sync(0xffffffffu, v, 4);
    v += __shfl_xor_sync(0xffffffffu, v, 2);
    v += __shfl_xor_sync(0xffffffffu, v, 1);
    return v;
}
__device__ __forceinline__ float warp_max(float v) {
    v = fmaxf(v, __shfl_xor_sync(0xffffffffu, v, 16));
    v = fmaxf(v, __shfl_xor_sync(0xffffffffu, v, 8));
    v = fmaxf(v, __shfl_xor_sync(0xffffffffu, v, 4));
    v = fmaxf(v, __shfl_xor_sync(0xffffffffu, v, 2));
    v = fmaxf(v, __shfl_xor_sync(0xffffffffu, v, 1));
    return v;
}
__device__ __forceinline__ u64 pk2(float lo, float hi) {
    u64 r; asm("mov.b64 %0, {%1,%2};" : "=l"(r) : "f"(lo), "f"(hi)); return r;
}
__device__ __forceinline__ void up2(u64 v, float& lo, float& hi) {
    asm("mov.b64 {%0,%1}, %2;" : "=f"(lo), "=f"(hi) : "l"(v));
}
__device__ __forceinline__ u64 f2mul(u64 a, u64 b) {
    u64 d; asm("mul.rn.f32x2 %0, %1, %2;" : "=l"(d) : "l"(a), "l"(b)); return d;
}
__device__ __forceinline__ u64 f2fma(u64 a, u64 b, u64 c) {
    u64 d; asm("fma.rn.f32x2 %0, %1, %2, %3;" : "=l"(d) : "l"(a), "l"(b), "l"(c)); return d;
}

// 8-value warp reduction: 9 shuffles. Lane ends holding full sum of cp[(lane>>2)&7].
__device__ __forceinline__ float warp_sum8(const float* cp, int lane) {
    const bool b4 = (lane & 16) != 0;
    const bool b3 = (lane & 8) != 0;
    const bool b2 = (lane & 4) != 0;
    float v0, v1, v2, v3;
    {
        float s, r;
        s = b4 ? cp[0] : cp[4]; r = __shfl_xor_sync(0xffffffffu, s, 16);
        v0 = (b4 ? cp[4] : cp[0]) + r;
        s = b4 ? cp[1] : cp[5]; r = __shfl_xor_sync(0xffffffffu, s, 16);
        v1 = (b4 ? cp[5] : cp[1]) + r;
        s = b4 ? cp[2] : cp[6]; r = __shfl_xor_sync(0xffffffffu, s, 16);
        v2 = (b4 ? cp[6] : cp[2]) + r;
        s = b4 ? cp[3] : cp[7]; r = __shfl_xor_sync(0xffffffffu, s, 16);
        v3 = (b4 ? cp[7] : cp[3]) + r;
    }
    float w0, w1;
    {
        float s, r;
        s = b3 ? v0 : v2; r = __shfl_xor_sync(0xffffffffu, s, 8);
        w0 = (b3 ? v2 : v0) + r;
        s = b3 ? v1 : v3; r = __shfl_xor_sync(0xffffffffu, s, 8);
        w1 = (b3 ? v3 : v1) + r;
    }
    float u;
    {
        float s = b2 ? w0 : w1;
        float r = __shfl_xor_sync(0xffffffffu, s, 4);
        u = (b2 ? w1 : w0) + r;
    }
    u += __shfl_xor_sync(0xffffffffu, u, 2);
    u += __shfl_xor_sync(0xffffffffu, u, 1);
    return u;
}

// ---------------- Kernel AB: fg mask + anomaly (R8 version) -------------------
// Blocks [0,64): A (fg mask), 576 thr, thread per patch. Blocks [64,64+2048):
// B (anomaly), 18 warps per block, warp per row.
__global__ void __launch_bounds__(576) kab(const float* __restrict__ x,
                                           const float* __restrict__ text,
                                           const float* __restrict__ attn) {
    const int tid = threadIdx.x;
    const int lane = tid & 31, w = tid >> 5;

    if (blockIdx.x < 64) {
        if (blockIdx.x == 0 && tid == 0) {   // reset accumulators (pre-kc1)
            g_n = 0.0; g_s1 = 0.0; g_s2 = 0.0; g_mxbits = 0u;
        }
        // ---- A: foreground mask ----
        __shared__ float sp[18];
        __shared__ float bcast;
        const int b = blockIdx.x;
        const int p = tid;

        const float* base = attn + (size_t)b * HH * (size_t)S2 + 1 + p;
        float a = 0.f;
        #pragma unroll
        for (int h = 0; h < HH; h++) a += __ldg(base + (size_t)h * S2);
        a *= (1.0f / 12.0f);

        float v = warp_sum(a);
        if (lane == 0) sp[w] = v;
        __syncthreads();
        if (w == 0) {
            float t = (lane < 18) ? sp[lane] : 0.f;
            t = warp_sum(t);
            if (lane == 0) bcast = t;
        }
        __syncthreads();
        const float mu = bcast * (1.0f / 576.0f);
        const float d = a - mu;
        __syncthreads();

        v = warp_sum(d * d);
        if (lane == 0) sp[w] = v;
        __syncthreads();
        if (w == 0) {
            float t = (lane < 18) ? sp[lane] : 0.f;
            t = warp_sum(t);
            if (lane == 0) bcast = t;
        }
        __syncthreads();
        const float sigma = sqrtf(bcast * (1.0f / 575.0f));

        g_fg[p * BB + b] = (a > mu + 1.5f * sigma) ? 1.0f : 0.0f;
    } else {
        // ---- B: per-row anomaly (warp per row) ----
        const int r = (blockIdx.x - 64) * 18 + w;
        const int b = r & (BB - 1);

        const float4* xr = (const float4*)x + (size_t)(r + BB) * (DD / 4);
        const float4* tr = (const float4*)text + (size_t)b * (DD / 4);

        float ss = 0.f, st = 0.f, tt = 0.f;
        #pragma unroll
        for (int it = 0; it < 6; it++) {
            const float4 xv = __ldg(xr + it * 32 + lane);
            const float4 tv = __ldg(tr + it * 32 + lane);
            ss += xv.x * xv.x + xv.y * xv.y + xv.z * xv.z + xv.w * xv.w;
            st += xv.x * tv.x + xv.y * tv.y + xv.z * tv.z + xv.w * tv.w;
            tt += tv.x * tv.x + tv.y * tv.y + tv.z * tv.z + tv.w * tv.w;
        }
        ss = warp_sum(ss);
        st = warp_sum(st);
        tt = warp_sum(tt);

        if (lane == 0) {
            const float pn = sqrtf(ss);
            const float tn = sqrtf(tt);
            const float sim = st / (fmaxf(pn, EPSC) * fmaxf(tn, EPSC));
            g_anom[r] = pn * (1.0f - fmaxf(sim, 0.0f));
        }
    }
}

// ---------------- Kernel C1: distributed stats (288 blocks x 128) ------------
// One element per thread. Float partials within block, double atomics across.
// var computed later as (s2 - mu^2*n)/(n-1) in double — exact identity since
// mu = s1/n; double kills the cancellation risk of single-pass variance.
__global__ void __launch_bounds__(128) kc1() {
    const int tid = threadIdx.x;
    const int lane = tid & 31, w = tid >> 5;
    const int i = blockIdx.x * 128 + tid;

    const float a = g_anom[i];
    const float f = g_fg[i];
    const float bg = 1.f - f;

    float n  = warp_sum(bg);
    float s1 = warp_sum(bg * a);
    float s2 = warp_sum(bg * a * a);
    float mx = warp_max(a);

    __shared__ float r0[4], r1[4], r2[4], r3[4];
    if (lane == 0) { r0[w] = n; r1[w] = s1; r2[w] = s2; r3[w] = mx; }
    __syncthreads();
    if (w == 0 && lane == 0) {
        const float bn  = r0[0] + r0[1] + r0[2] + r0[3];
        const float bs1 = r1[0] + r1[1] + r1[2] + r1[3];
        const float bs2 = r2[0] + r2[1] + r2[2] + r2[3];
        const float bmx = fmaxf(fmaxf(r3[0], r3[1]), fmaxf(r3[2], r3[3]));
        atomicAdd(&g_n,  (double)bn);
        atomicAdd(&g_s1, (double)bs1);
        atomicAdd(&g_s2, (double)bs2);
        atomicMax(&g_mxbits, __float_as_uint(fmaxf(bmx, 0.f)));
    }
}

// ---------------- Kernel C2: gate (192 blocks x 192) --------------------------
__global__ void __launch_bounds__(192) kc2() {
    __shared__ float sthr;
    if (threadIdx.x == 0) {
        const double n  = g_n;
        const double s1 = g_s1;
        const double s2 = g_s2;
        const double mu = s1 / fmax(n, 1.0);
        const double var = fmax((s2 - mu * mu * n) / fmax(n - 1.0, 1.0), 0.0);
        sthr = (n > 0.0) ? (float)(mu + (double)BETA_C * sqrt(var))
                         : __uint_as_float(g_mxbits);
    }
    __syncthreads();
    const float thr = sthr;
    const int r = blockIdx.x * 192 + threadIdx.x;
    const float a = g_anom[r];
    const float f = g_fg[r];
    g_gate[r] = f + (1.f - f) * (1.0f / (1.0f + __expf(-GAMMA_C * (thr - a))));
}

// ---------------- Kernel D: coeff + proj + blend, software-pipelined ----------
// 192 threads, thread owns 4 cols; pc in 32 regs. Batches of 4 rows; ping-pong
// smem buffers give ONE __syncthreads per batch: batch n's reduction overlaps
// batch n-1's projection+store. Reverse block order for L2 reuse of x.
__global__ void __launch_bounds__(192) kd_out(const float* __restrict__ x,
                                              const float* __restrict__ pc,
                                              float* __restrict__ out) {
    const int tid = threadIdx.x;
    const int warp = tid >> 5;
    const int lane = tid & 31;

    u64 pc0[KK], pc1[KK];
    #pragma unroll
    for (int k = 0; k < KK; k++) {
        const float4 v = __ldg((const float4*)pc + k * 192 + tid);
        pc0[k] = pk2(v.x, v.y);
        pc1[k] = pk2(v.z, v.w);
    }

    __shared__ float redp[2][4 * 6 * 8];            // [buf][row][warp][k]
    __shared__ __align__(16) float cfin[2][4 * 8];  // [buf][row][k]

    const int base = (DBLK - 1 - (int)blockIdx.x) * 32;
    const int kk = lane >> 2;
    const bool kl = (lane & 3) == 0;

    u64 xp0[4], xp1[4];
    float gp[4];

    // ---- prologue: batch 0 load + partials ----
    #pragma unroll
    for (int j = 0; j < 4; j++) {
        const int r = base + j;
        const float4 xv = __ldg((const float4*)x + (size_t)(r + BB) * (DD / 4) + tid);
        xp0[j] = pk2(xv.x, xv.y);
        xp1[j] = pk2(xv.z, xv.w);
        gp[j] = __ldg(&g_gate[r]);
        float cp[KK];
        #pragma unroll
        for (int k = 0; k < KK; k++) {
            const u64 acc = f2fma(xp1[j], pc1[k], f2mul(xp0[j], pc0[k]));
            float lo, hi; up2(acc, lo, hi);
            cp[k] = lo + hi;
        }
        const float u = warp_sum8(cp, lane);
        if (kl) redp[0][(j * 6 + warp) * 8 + kk] = u;
    }
    __syncthreads();
    if (tid < 32) {
        const int row = tid >> 3, k = tid & 7;
        float s = 0.f;
        #pragma unroll
        for (int ww = 0; ww < 6; ww++) s += redp[0][(row * 6 + ww) * 8 + k];
        cfin[0][row * 8 + k] = s;
    }

    // ---- main loop: batches 1..7 ----
    for (int n = 1; n < 8; n++) {
        const int pn = n & 1;
        u64 xc0[4], xc1[4];
        float gc[4];
        const int i0 = n * 4;
        #pragma unroll
        for (int j = 0; j < 4; j++) {
            const int r = base + i0 + j;
            const float4 xv = __ldg((const float4*)x + (size_t)(r + BB) * (DD / 4) + tid);
            xc0[j] = pk2(xv.x, xv.y);
            xc1[j] = pk2(xv.z, xv.w);
            gc[j] = __ldg(&g_gate[r]);
            float cp[KK];
            #pragma unroll
            for (int k = 0; k < KK; k++) {
                const u64 acc = f2fma(xc1[j], pc1[k], f2mul(xc0[j], pc0[k]));
                float lo, hi; up2(acc, lo, hi);
                cp[k] = lo + hi;
            }
            const float u = warp_sum8(cp, lane);
            if (kl) redp[pn][(j * 6 + warp) * 8 + kk] = u;
        }
        __syncthreads();   // redp[pn] ready; cfin[1-pn] from batch n-1 visible
        if (tid < 32) {
            const int row = tid >> 3, k = tid & 7;
            float s = 0.f;
            #pragma unroll
            for (int ww = 0; ww < 6; ww++) s += redp[pn][(row * 6 + ww) * 8 + k];
            cfin[pn][row * 8 + k] = s;
        }
        // proj + blend + store for batch n-1 (overlaps next batch's latency)
        #pragma unroll
        for (int j = 0; j < 4; j++) {
            const int r = base + (n - 1) * 4 + j;
            const float g = gp[j];
            const float4 cA = *(const float4*)(cfin[1 - pn] + j * 8);
            const float4 cB = *(const float4*)(cfin[1 - pn] + j * 8 + 4);

            u64 cc = pk2(cA.x, cA.x);
            u64 q0 = f2mul(cc, pc0[0]);
            u64 q1 = f2mul(cc, pc1[0]);
            cc = pk2(cA.y, cA.y); q0 = f2fma(cc, pc0[1], q0); q1 = f2fma(cc, pc1[1], q1);
            cc = pk2(cA.z, cA.z); q0 = f2fma(cc, pc0[2], q0); q1 = f2fma(cc, pc1[2], q1);
            cc = pk2(cA.w, cA.w); q0 = f2fma(cc, pc0[3], q0); q1 = f2fma(cc, pc1[3], q1);
            cc = pk2(cB.x, cB.x); q0 = f2fma(cc, pc0[4], q0); q1 = f2fma(cc, pc1[4], q1);
            cc = pk2(cB.y, cB.y); q0 = f2fma(cc, pc0[5], q0); q1 = f2fma(cc, pc1[5], q1);
            cc = pk2(cB.z, cB.z); q0 = f2fma(cc, pc0[6], q0); q1 = f2fma(cc, pc1[6], q1);
            cc = pk2(cB.w, cB.w); q0 = f2fma(cc, pc0[7], q0); q1 = f2fma(cc, pc1[7], q1);

            const float og = 1.0f - g;
            const u64 g2  = pk2(g, g);
            const u64 og2 = pk2(og, og);
            const u64 o0 = f2fma(g2, xp0[j], f2mul(og2, q0));
            const u64 o1 = f2fma(g2, xp1[j], f2mul(og2, q1));
            float a0, a1, a2, a3;
            up2(o0, a0, a1);
            up2(o1, a2, a3);
            ((float4*)out)[(size_t)(r + BB) * (DD / 4) + tid] =
                make_float4(a0, a1, a2, a3);
        }
        // rotate previous-batch registers
        #pragma unroll
        for (int j = 0; j < 4; j++) { xp0[j] = xc0[j]; xp1[j] = xc1[j]; gp[j] = gc[j]; }
    }

    // ---- epilogue: batch 7 projection (cfin[1] written after last sync) ----
    __syncthreads();
    #pragma unroll
    for (int j = 0; j < 4; j++) {
        const int r = base + 28 + j;
        const float g = gp[j];
        const float4 cA = *(const float4*)(cfin[1] + j * 8);
        const float4 cB = *(const float4*)(cfin[1] + j * 8 + 4);

        u64 cc = pk2(cA.x, cA.x);
        u64 q0 = f2mul(cc, pc0[0]);
        u64 q1 = f2mul(cc, pc1[0]);
        cc = pk2(cA.y, cA.y); q0 = f2fma(cc, pc0[1], q0); q1 = f2fma(cc, pc1[1], q1);
        cc = pk2(cA.z, cA.z); q0 = f2fma(cc, pc0[2], q0); q1 = f2fma(cc, pc1[2], q1);
        cc = pk2(cA.w, cA.w); q0 = f2fma(cc, pc0[3], q0); q1 = f2fma(cc, pc1[3], q1);
        cc = pk2(cB.x, cB.x); q0 = f2fma(cc, pc0[4], q0); q1 = f2fma(cc, pc1[4], q1);
        cc = pk2(cB.y, cB.y); q0 = f2fma(cc, pc0[5], q0); q1 = f2fma(cc, pc1[5], q1);
        cc = pk2(cB.z, cB.z); q0 = f2fma(cc, pc0[6], q0); q1 = f2fma(cc, pc1[6], q1);
        cc = pk2(cB.w, cB.w); q0 = f2fma(cc, pc0[7], q0); q1 = f2fma(cc, pc1[7], q1);

        const float og = 1.0f - g;
        const u64 g2  = pk2(g, g);
        const u64 og2 = pk2(og, og);
        const u64 o0 = f2fma(g2, xp0[j], f2mul(og2, q0));
        const u64 o1 = f2fma(g2, xp1[j], f2mul(og2, q1));
        float a0, a1, a2, a3;
        up2(o0, a0, a1);
        up2(o1, a2, a3);
        ((float4*)out)[(size_t)(r + BB) * (DD / 4) + tid] =
            make_float4(a0, a1, a2, a3);
    }
}

// ---------------- launch ------------------------------------------------------
extern "C" void kernel_launch(void* const* d_in, const int* in_sizes, int n_in,
                              void* d_out, int out_size) {
    const float* x    = (const float*)d_in[0];
    const float* attn = (const float*)d_in[1];
    const float* text = (const float*)d_in[2];
    const float* pc   = (const float*)d_in[3];
    float* out = (float*)d_out;

    // cls token pass-through: out[0] = x[0]
    cudaMemcpyAsync(out, x, (size_t)BB * DD * sizeof(float),
                    cudaMemcpyDeviceToDevice);

    kab<<<64 + 2048, 576>>>(x, text, attn);
    kc1<<<ROWS / 128, 128>>>();
    kc2<<<ROWS / 192, 192>>>();
    kd_out<<<DBLK, 192>>>(x, pc, out);
}